// round 17
// baseline (speedup 1.0000x reference)
#include <cuda_runtime.h>
#include <cuda_fp16.h>
#include <cstdint>

// RetNet retention via exact chunked linear-attention form (R17).
//   A: partial  P_c = K'^T [V | 1]  (reads fp32 K/V, writes ONLY P fp16)
//   B: prefix scan T_{c+1} = g^64 (T_c + P_c)
//   C: O = g^{iloc} Q T_c + intra-chunk  (reads fp32 Q/K/V, converts in-kernel)
// B=2, H=16, L=2048, DK=DV=128, chunk C=64.
namespace {
constexpr int Lc  = 2048;
constexpr int Hc  = 16;
constexpr int Bc  = 2;
constexpr int DKc = 128;
constexpr int CH  = 64;
constexpr int NC  = Lc / CH;            // 32
constexpr int NBH = Bc * Hc;            // 32
constexpr int PCOLS = 136;              // 128 dv + z col + 7 pad
constexpr int KV_STRIDE = 136;
constexpr int TS_STRIDE = 152;

constexpr size_t PT_ELEMS = (size_t)NBH * NC * DKc * PCOLS;  // 17825792
}

__device__ __half g_P[PT_ELEMS];    // chunk partials fp16
__device__ __half g_T[PT_ELEMS];    // prefix states fp16

__device__ __forceinline__ void ldsm4(uint32_t& r0, uint32_t& r1, uint32_t& r2, uint32_t& r3,
                                      uint32_t addr) {
    asm volatile("ldmatrix.sync.aligned.m8n8.x4.shared.b16 {%0,%1,%2,%3}, [%4];"
                 : "=r"(r0), "=r"(r1), "=r"(r2), "=r"(r3) : "r"(addr));
}
__device__ __forceinline__ void ldsm4t(uint32_t& r0, uint32_t& r1, uint32_t& r2, uint32_t& r3,
                                       uint32_t addr) {
    asm volatile("ldmatrix.sync.aligned.m8n8.x4.trans.shared.b16 {%0,%1,%2,%3}, [%4];"
                 : "=r"(r0), "=r"(r1), "=r"(r2), "=r"(r3) : "r"(addr));
}
__device__ __forceinline__ void mma_f16(float c[4],
                                        uint32_t a0, uint32_t a1, uint32_t a2, uint32_t a3,
                                        uint32_t b0, uint32_t b1) {
    asm volatile(
        "mma.sync.aligned.m16n8k16.row.col.f32.f16.f16.f32 "
        "{%0,%1,%2,%3}, {%4,%5,%6,%7}, {%8,%9}, {%0,%1,%2,%3};\n"
        : "+f"(c[0]), "+f"(c[1]), "+f"(c[2]), "+f"(c[3])
        : "r"(a0), "r"(a1), "r"(a2), "r"(a3), "r"(b0), "r"(b1));
}
__device__ __forceinline__ uint32_t h2bits(__half2 h) {
    return *reinterpret_cast<uint32_t*>(&h);
}

#define CP_ASYNC16(dst, src) \
    asm volatile("cp.async.cg.shared.global [%0], [%1], 16;" :: "r"(dst), "l"(src) : "memory")
#define CP_COMMIT() asm volatile("cp.async.commit_group;" ::: "memory")
#define CP_WAIT0()  asm volatile("cp.async.wait_group 0;"  ::: "memory")

__device__ __forceinline__ float head_lg2(int h) {
    return log1pf(-exp2f(-5.0f - (float)h)) * 1.4426950408889634f;
}

// ============ kernel A: chunk partial P = K'^T [V | 1]  (fp32 in, P fp16 out) ============
// grid (NC, NBH), 128 threads.
__global__ __launch_bounds__(128, 5)
void partial_kernel(const float* __restrict__ k,
                    const float* __restrict__ v)
{
    extern __shared__ __align__(16) char smraw[];
    __half* Ka = reinterpret_cast<__half*>(smraw);            // [64][136]
    __half* Va = Ka + CH * KV_STRIDE;                         // [64][152] augmented
    const uint32_t KaU = (uint32_t)__cvta_generic_to_shared(Ka);
    const uint32_t VaU = (uint32_t)__cvta_generic_to_shared(Va);

    const int tid  = threadIdx.x;
    const int lane = tid & 31;
    const int warp = tid >> 5;
    const int lr   = lane >> 2;
    const int lc   = lane & 3;
    const int l7 = lane & 7;
    const int g  = lane >> 3;
    const int a_row  = l7 + (g & 1) * 8;
    const int a_col8 = (g >> 1) * 8;

    const int c  = blockIdx.x;
    const int bh = blockIdx.y;
    const int h  = bh & 15;
    const int j0 = c * CH;
    const float lg2 = head_lg2(h);

    const size_t base = (size_t)bh * Lc * DKc + (size_t)j0 * DKc;
    const float* ks = k + base;
    const float* vs = v + base;

    // convert: K (scaled by gamma^{-r}) -> smem ; V -> smem
    #pragma unroll
    for (int t = 0; t < 16; t++) {
        int idx = tid + t * 128;
        int r   = idx >> 5;       // 0..63
        int c4  = idx & 31;
        const float cj = exp2f(-lg2 * (float)r);
        float4 gk = *(const float4*)(ks + (size_t)r * DKc + c4 * 4);
        uint2 uk;
        uk.x = h2bits(__floats2half2_rn(gk.x * cj, gk.y * cj));
        uk.y = h2bits(__floats2half2_rn(gk.z * cj, gk.w * cj));
        *(uint2*)(Ka + r * KV_STRIDE + c4 * 4) = uk;

        float4 gv = *(const float4*)(vs + (size_t)r * DKc + c4 * 4);
        uint2 uv;
        uv.x = h2bits(__floats2half2_rn(gv.x, gv.y));
        uv.y = h2bits(__floats2half2_rn(gv.z, gv.w));
        *(uint2*)(Va + r * TS_STRIDE + c4 * 4) = uv;
    }
    // augmentation: col 128 = 1.0, cols 129..151 = 0
    if (tid < 64) {
        __half* row = Va + tid * TS_STRIDE;
        row[128] = __float2half_rn(1.0f);
        #pragma unroll
        for (int cc = 129; cc < 152; cc++) row[cc] = __float2half_rn(0.0f);
    }
    __syncthreads();

    // A-fragments of K'^T via ldsm trans; mapping a0=r0, a1=r2, a2=r1, a3=r3.
    uint32_t afr[2][4][4];
    #pragma unroll
    for (int mt = 0; mt < 2; mt++)
        #pragma unroll
        for (int kt = 0; kt < 4; kt++) {
            uint32_t r0, r1, r2, r3;
            uint32_t addr = KaU + ((uint32_t)((kt * 16 + a_row) * KV_STRIDE
                                              + warp * 32 + mt * 16 + a_col8)) * 2;
            ldsm4t(r0, r1, r2, r3, addr);
            afr[mt][kt][0] = r0; afr[mt][kt][1] = r2;
            afr[mt][kt][2] = r1; afr[mt][kt][3] = r3;
        }

    __half* Pout = g_P + (size_t)(bh * NC + c) * DKc * PCOLS;

    #pragma unroll
    for (int ntb = 0; ntb < 9; ntb++) {
        uint32_t bfr[4][4];
        #pragma unroll
        for (int kt = 0; kt < 4; kt++) {
            ldsm4t(bfr[kt][0], bfr[kt][1], bfr[kt][2], bfr[kt][3],
                   VaU + ((uint32_t)((kt * 16 + a_row) * TS_STRIDE + ntb * 16 + a_col8)) * 2);
        }
        #pragma unroll
        for (int mt = 0; mt < 2; mt++) {
            #pragma unroll
            for (int nh = 0; nh < 2; nh++) {
                if (ntb == 8 && nh == 1) continue;   // cols >=136 discarded
                float acc[4] = {0.0f, 0.0f, 0.0f, 0.0f};
                #pragma unroll
                for (int kt = 0; kt < 4; kt++)
                    mma_f16(acc, afr[mt][kt][0], afr[mt][kt][1], afr[mt][kt][2], afr[mt][kt][3],
                            bfr[kt][nh * 2], bfr[kt][nh * 2 + 1]);
                const int dk0 = warp * 32 + mt * 16 + lr;
                const int col = ntb * 16 + nh * 8 + 2 * lc;
                *(__half2*)(Pout + (size_t)dk0 * PCOLS + col) =
                    __floats2half2_rn(acc[0], acc[1]);
                *(__half2*)(Pout + (size_t)(dk0 + 8) * PCOLS + col) =
                    __floats2half2_rn(acc[2], acc[3]);
            }
        }
    }
}

// ============ kernel B: prefix scan T_{c+1} = g^64 (T_c + P_c), prefetched ============
// grid (17 col-slabs of 8, NBH), 128 threads (thread = dk row).
__global__ __launch_bounds__(128)
void scan_kernel()
{
    const int s  = blockIdx.x;
    const int bh = blockIdx.y;
    const int t  = threadIdx.x;
    const float g64 = exp2f(head_lg2(bh & 15) * 64.0f);

    const __half* P = g_P + (size_t)bh * NC * DKc * PCOLS;
    __half*       T = g_T + (size_t)bh * NC * DKc * PCOLS;
    const size_t offs = (size_t)t * PCOLS + s * 8;
    const size_t cstride = (size_t)DKc * PCOLS;

    // T_0 = 0
    {
        uint4 z = make_uint4(0, 0, 0, 0);
        *(uint4*)(T + offs) = z;
    }

    float acc[8] = {0, 0, 0, 0, 0, 0, 0, 0};
    uint4 nxt = *(const uint4*)(P + offs);   // chunk 0
    #pragma unroll 4
    for (int c = 0; c < NC - 1; c++) {
        uint4 cur = nxt;
        if (c + 1 < NC - 1) nxt = *(const uint4*)(P + (c + 1) * cstride + offs);
        const __half2* ph = reinterpret_cast<const __half2*>(&cur);
        #pragma unroll
        for (int e = 0; e < 4; e++) {
            float2 p = __half22float2(ph[e]);
            acc[2 * e]     = g64 * (acc[2 * e]     + p.x);
            acc[2 * e + 1] = g64 * (acc[2 * e + 1] + p.y);
        }
        uint4 o;
        ((uint32_t*)&o)[0] = h2bits(__floats2half2_rn(acc[0], acc[1]));
        ((uint32_t*)&o)[1] = h2bits(__floats2half2_rn(acc[2], acc[3]));
        ((uint32_t*)&o)[2] = h2bits(__floats2half2_rn(acc[4], acc[5]));
        ((uint32_t*)&o)[3] = h2bits(__floats2half2_rn(acc[6], acc[7]));
        *(uint4*)(T + (c + 1) * cstride + offs) = o;
    }
}

// ============ kernel C: output = intra(chunk) + g^{iloc} Q T_c ; denom ; RMS ============
// grid (NC, NBH), 128 threads, 3 CTAs/SM. Reads fp32 Q/K/V directly.
__global__ __launch_bounds__(128, 3)
void retnet_out_kernel(const float* __restrict__ q,
                       const float* __restrict__ k,
                       const float* __restrict__ v,
                       float* __restrict__ out)
{
    extern __shared__ __align__(16) char smraw[];
    __half* Ks = reinterpret_cast<__half*>(smraw);            // [64][136] (Q staged here first)
    __half* Vs = Ks + CH * KV_STRIDE;                         // [64][136]
    __half* Ts = Vs + CH * KV_STRIDE;                         // [128][152]
    const uint32_t KsU = (uint32_t)__cvta_generic_to_shared(Ks);
    const uint32_t VsU = (uint32_t)__cvta_generic_to_shared(Vs);
    const uint32_t TsU = (uint32_t)__cvta_generic_to_shared(Ts);

    const int tid  = threadIdx.x;
    const int lane = tid & 31;
    const int warp = tid >> 5;
    const int lr   = lane >> 2;
    const int lc   = lane & 3;
    const int l7 = lane & 7;
    const int g  = lane >> 3;
    const int a_row  = l7 + (g & 1) * 8;
    const int a_col8 = (g >> 1) * 8;
    const int kb_row  = l7 + (g >> 1) * 8;
    const int kb_col8 = (g & 1) * 8;

    const int c  = blockIdx.x;
    const int bh = blockIdx.y;
    const int b  = bh >> 4;
    const int h  = bh & 15;
    const int i0 = c * CH;

    const size_t base = (size_t)bh * Lc * DKc + (size_t)i0 * DKc;
    const float* qb = q + base;
    const float* kb2 = k + base;
    const float* vb2 = v + base;
    const __half* th = g_T + (size_t)(bh * NC + c) * DKc * PCOLS;

    const float lg2 = head_lg2(h);
    const int il0 = warp * 16 + lr;
    const int il1 = il0 + 8;
    const float R0 = exp2f(lg2 * (float)il0);
    const float R1 = exp2f(lg2 * (float)il1);

    // (1) issue T cp.async first (into Ts; no conflict with Q staging in Ks)
    #pragma unroll
    for (int t = 0; t < 17; t++) {
        int idx = tid + t * 128;
        int r   = idx / 17;
        int ch  = idx % 17;
        CP_ASYNC16(TsU + (uint32_t)(r * TS_STRIDE + ch * 8) * 2, th + (size_t)r * PCOLS + ch * 8);
    }
    CP_COMMIT();

    // (2) stage Q fp32->fp16 into Ks, pull qa fragments
    #pragma unroll
    for (int t = 0; t < 16; t++) {
        int idx = tid + t * 128;
        int r   = idx >> 5;       // 0..63
        int c4  = idx & 31;
        float4 gld = *(const float4*)(qb + (size_t)r * DKc + c4 * 4);
        uint2 u;
        u.x = h2bits(__floats2half2_rn(gld.x, gld.y));
        u.y = h2bits(__floats2half2_rn(gld.z, gld.w));
        *(uint2*)(Ks + r * KV_STRIDE + c4 * 4) = u;
    }
    __syncthreads();
    uint32_t qa[8][4];
    #pragma unroll
    for (int kt = 0; kt < 8; kt++) {
        ldsm4(qa[kt][0], qa[kt][1], qa[kt][2], qa[kt][3],
              KsU + (uint32_t)((warp * 16 + a_row) * KV_STRIDE + kt * 16 + a_col8) * 2);
    }
    __syncthreads();

    // (3) stage K' (gamma^{-r} fold) and V fp32->fp16
    #pragma unroll
    for (int t = 0; t < 16; t++) {
        int idx = tid + t * 128;
        int r   = idx >> 5;
        int c4  = idx & 31;
        const float cj = exp2f(-lg2 * (float)r);
        float4 gk = *(const float4*)(kb2 + (size_t)r * DKc + c4 * 4);
        uint2 uk;
        uk.x = h2bits(__floats2half2_rn(gk.x * cj, gk.y * cj));
        uk.y = h2bits(__floats2half2_rn(gk.z * cj, gk.w * cj));
        *(uint2*)(Ks + r * KV_STRIDE + c4 * 4) = uk;

        float4 gv = *(const float4*)(vb2 + (size_t)r * DKc + c4 * 4);
        uint2 uv;
        uv.x = h2bits(__floats2half2_rn(gv.x, gv.y));
        uv.y = h2bits(__floats2half2_rn(gv.z, gv.w));
        *(uint2*)(Vs + r * KV_STRIDE + c4 * 4) = uv;
    }
    CP_WAIT0();
    __syncthreads();

    // (4) intra GEMM1: S = Q K'^T
    float scr[8][4];
    #pragma unroll
    for (int t = 0; t < 8; t++)
        #pragma unroll
        for (int e = 0; e < 4; e++) scr[t][e] = 0.0f;
    #pragma unroll
    for (int kt = 0; kt < 8; kt++) {
        #pragma unroll
        for (int nt = 0; nt < 4; nt++) {
            uint32_t b0, b1, b2, b3;
            ldsm4(b0, b1, b2, b3,
                  KsU + (uint32_t)((nt * 16 + kb_row) * KV_STRIDE + kt * 16 + kb_col8) * 2);
            mma_f16(scr[nt * 2],     qa[kt][0], qa[kt][1], qa[kt][2], qa[kt][3], b0, b1);
            mma_f16(scr[nt * 2 + 1], qa[kt][0], qa[kt][1], qa[kt][2], qa[kt][3], b2, b3);
        }
    }

    // (5) decay + causal mask + intra rowsum + fp16 repack
    float rs0 = 0.0f, rs1 = 0.0f;
    uint32_t sa[4][4];
    #pragma unroll
    for (int t = 0; t < 8; t++) {
        const int jb = t * 8 + 2 * lc;
        float v0 = scr[t][0] * R0;
        float v1 = scr[t][1] * R0;
        float v2 = scr[t][2] * R1;
        float v3 = scr[t][3] * R1;
        if (jb     > il0) v0 = 0.0f;
        if (jb + 1 > il0) v1 = 0.0f;
        if (jb     > il1) v2 = 0.0f;
        if (jb + 1 > il1) v3 = 0.0f;
        rs0 += v0 + v1;
        rs1 += v2 + v3;
        const int u  = t >> 1;
        const int hi = (t & 1) * 2;
        sa[u][hi]     = h2bits(__floats2half2_rn(v0, v1));
        sa[u][hi + 1] = h2bits(__floats2half2_rn(v2, v3));
    }

    // (6) inter GEMM: ocI = Q · T  (n = 136 incl z col 128)
    float ocI[18][4];
    #pragma unroll
    for (int t = 0; t < 18; t++)
        #pragma unroll
        for (int e = 0; e < 4; e++) ocI[t][e] = 0.0f;
    #pragma unroll
    for (int ntb = 0; ntb < 9; ntb++) {
        #pragma unroll
        for (int kt = 0; kt < 8; kt++) {
            uint32_t b0, b1, b2, b3;
            ldsm4t(b0, b1, b2, b3,
                   TsU + (uint32_t)((kt * 16 + a_row) * TS_STRIDE + ntb * 16 + a_col8) * 2);
            mma_f16(ocI[ntb * 2],     qa[kt][0], qa[kt][1], qa[kt][2], qa[kt][3], b0, b1);
            mma_f16(ocI[ntb * 2 + 1], qa[kt][0], qa[kt][1], qa[kt][2], qa[kt][3], b2, b3);
        }
    }
    #pragma unroll
    for (int t = 0; t < 18; t++) {
        ocI[t][0] *= R0; ocI[t][1] *= R0;
        ocI[t][2] *= R1; ocI[t][3] *= R1;
    }

    // (7) intra GEMM2 accumulates on top: O += S~ · V
    #pragma unroll
    for (int kt2 = 0; kt2 < 4; kt2++) {
        #pragma unroll
        for (int dt = 0; dt < 8; dt++) {
            uint32_t b0, b1, b2, b3;
            ldsm4t(b0, b1, b2, b3,
                   VsU + (uint32_t)((kt2 * 16 + a_row) * KV_STRIDE + dt * 16 + a_col8) * 2);
            mma_f16(ocI[dt * 2],     sa[kt2][0], sa[kt2][1], sa[kt2][2], sa[kt2][3], b0, b1);
            mma_f16(ocI[dt * 2 + 1], sa[kt2][0], sa[kt2][1], sa[kt2][2], sa[kt2][3], b2, b3);
        }
    }

    // (8) denominator (z col 128 lives in frag ntb=8 low half at 2lc==0)
    if (lc == 0) { rs0 += ocI[16][0]; rs1 += ocI[16][2]; }
    rs0 += __shfl_xor_sync(0xffffffffu, rs0, 1);
    rs0 += __shfl_xor_sync(0xffffffffu, rs0, 2);
    rs1 += __shfl_xor_sync(0xffffffffu, rs1, 1);
    rs1 += __shfl_xor_sync(0xffffffffu, rs1, 2);
    const float dn0 = 1.0f / fmaxf(fabsf(rs0), 1.0f);
    const float dn1 = 1.0f / fmaxf(fabsf(rs1), 1.0f);

    // (9) normalize + RMS + write
    float ssq0 = 0.0f, ssq1 = 0.0f;
    #pragma unroll
    for (int t = 0; t < 16; t++) {
        ocI[t][0] *= dn0; ocI[t][1] *= dn0;
        ocI[t][2] *= dn1; ocI[t][3] *= dn1;
        ssq0 += ocI[t][0] * ocI[t][0] + ocI[t][1] * ocI[t][1];
        ssq1 += ocI[t][2] * ocI[t][2] + ocI[t][3] * ocI[t][3];
    }
    ssq0 += __shfl_xor_sync(0xffffffffu, ssq0, 1);
    ssq0 += __shfl_xor_sync(0xffffffffu, ssq0, 2);
    ssq1 += __shfl_xor_sync(0xffffffffu, ssq1, 1);
    ssq1 += __shfl_xor_sync(0xffffffffu, ssq1, 2);
    const float sc0 = rsqrtf(ssq0 * (1.0f / 128.0f) + 1e-6f);
    const float sc1 = rsqrtf(ssq1 * (1.0f / 128.0f) + 1e-6f);

    float* po0 = out + (((size_t)b * Lc + (i0 + il0)) * Hc + h) * DKc;
    float* po1 = out + (((size_t)b * Lc + (i0 + il1)) * Hc + h) * DKc;
    #pragma unroll
    for (int t = 0; t < 16; t++) {
        const int d = t * 8 + 2 * lc;
        float2 w0, w1;
        w0.x = ocI[t][0] * sc0; w0.y = ocI[t][1] * sc0;
        w1.x = ocI[t][2] * sc1; w1.y = ocI[t][3] * sc1;
        *(float2*)(po0 + d) = w0;
        *(float2*)(po1 + d) = w1;
    }
}

extern "C" void kernel_launch(void* const* d_in, const int* in_sizes, int n_in,
                              void* d_out, int out_size)
{
    const float* q = (const float*)d_in[0];
    const float* k = (const float*)d_in[1];
    const float* v = (const float*)d_in[2];
    float* out = (float*)d_out;

    // A) chunk partials (fp32 in, P fp16 out)
    {
        const int smem = (CH * KV_STRIDE + CH * TS_STRIDE) * 2;
        cudaFuncSetAttribute(partial_kernel,
                             cudaFuncAttributeMaxDynamicSharedMemorySize, smem);
        dim3 grid(NC, NBH);
        partial_kernel<<<grid, 128, smem>>>(k, v);
    }
    // B) prefix scan
    {
        dim3 grid(17, NBH);
        scan_kernel<<<grid, 128>>>();
    }
    // C) fused output
    {
        const int smem = (2 * CH * KV_STRIDE + DKc * TS_STRIDE) * 2;
        cudaFuncSetAttribute(retnet_out_kernel,
                             cudaFuncAttributeMaxDynamicSharedMemorySize, smem);
        dim3 grid(NC, NBH);
        retnet_out_kernel<<<grid, 128, smem>>>(q, k, v, out);
    }
}